// round 7
// baseline (speedup 1.0000x reference)
#include <cuda_runtime.h>
#include <math.h>

#define B 128
#define L 1024
#define ROWS_PER_BLK 32
#define NBLK (B * L / ROWS_PER_BLK)     // 4096 blocks, 32 per batch
#define P_TX 10.0f
#define P_NOISE 6.2946e-14f

__device__ float g_bsum[NBLK];            // per-block partial sums of R
__device__ float g_inv[B];                // per-batch 1/sum
__device__ unsigned int g_cnt[B] = {};    // per-batch completion counters
__device__ unsigned int g_final = 0;      // final completion counter

__inline__ __device__ float warp_reduce(float v) {
    #pragma unroll
    for (int o = 16; o; o >>= 1) v += __shfl_down_sync(0xffffffffu, v, o);
    return v;
}

__device__ __forceinline__ unsigned int atom_add_acqrel(unsigned int* p) {
    unsigned int old;
    asm volatile("atom.add.acq_rel.gpu.u32 %0, [%1], 1;"
                 : "=r"(old) : "l"(p) : "memory");
    return old;
}

// Single fused kernel: 32 warps = 32 rows per block; hierarchical fence-free finalize.
__global__ void __launch_bounds__(1024) fused_kernel(const float* __restrict__ H,
                                                     const float* __restrict__ prob,
                                                     float* __restrict__ out) {
    const int wid  = threadIdx.x >> 5;
    const int lane = threadIdx.x & 31;
    const int row  = blockIdx.x * ROWS_PER_BLK + wid;       // global row in [0, B*L)
    const int b    = blockIdx.x >> 5;                        // 32 blocks per batch
    const int k    = row & (L - 1);

    __shared__ float sPy[L];             // P * y[b, :]  (4 KB)
    __shared__ float sR[ROWS_PER_BLK];

    // Stage Py: 512 threads, one full-line float4 each (2 y-values per float4)
    if (threadIdx.x < 512) {
        const float4* __restrict__ p4 =
            reinterpret_cast<const float4*>(prob + 2 * (size_t)b * L);
        float4 v = __ldg(p4 + threadIdx.x);
        sPy[2 * threadIdx.x]     = P_TX * v.y;
        sPy[2 * threadIdx.x + 1] = P_TX * v.w;
    }
    __syncthreads();

    const float4* __restrict__ h4 = reinterpret_cast<const float4*>(H + (size_t)row * L);
    const float4* __restrict__ s4 = reinterpret_cast<const float4*>(sPy);

    const int t_k    = k >> 2;           // float4 index holding the diagonal
    const int lane_k = t_k & 31;
    float acc  = 0.0f;
    float dval = 0.0f;                   // diagonal H[k,k], captured in-loop

    #pragma unroll
    for (int i = 0; i < 8; i++) {
        const int t = i * 32 + lane;
        float4 h = __ldcs(h4 + t);       // streaming: H read exactly once
        float4 p = s4[t];                // conflict-free LDS.128
        acc = fmaf(h.x * h.x, p.x, acc);
        acc = fmaf(h.y * h.y, p.y, acc);
        acc = fmaf(h.z * h.z, p.z, acc);
        acc = fmaf(h.w * h.w, p.w, acc);
        if (t == t_k) {                  // one lane, one iteration
            dval = (k & 1) ? ((k & 2) ? h.w : h.y)
                           : ((k & 2) ? h.z : h.x);
        }
    }

    acc  = warp_reduce(acc);
    dval = __shfl_sync(0xffffffffu, dval, lane_k);

    if (lane == 0) {
        float signal = dval * dval * sPy[k];
        float interf = acc - signal;
        sR[wid] = log1pf(signal / (interf + P_NOISE)) * 1.4426950408889634f;
    }
    __syncthreads();

    // Warp 0: block partial, completion protocol, tails
    if (wid != 0) return;

    float s = warp_reduce(sR[lane]);     // 32 per-row rates

    __shared__ bool sLastInBatch;        // only warp 0 reads/writes past here
    bool last_in_batch = false;
    if (lane == 0) {
        __stcg(&g_bsum[blockIdx.x], s);                  // L2 = coherence point
        unsigned int t = atom_add_acqrel(&g_cnt[b]);     // release orders the stcg
        last_in_batch = (t == (unsigned int)(32 - 1));
    }
    last_in_batch = __shfl_sync(0xffffffffu, last_in_batch, 0);
    (void)sLastInBatch;
    if (!last_in_batch) return;

    // ---- Per-batch tail: reduce this batch's 32 partials ----
    {
        float v = __ldcg(g_bsum + b * 32 + lane);
        v = warp_reduce(v);

        bool last_final = false;
        if (lane == 0) {
            __stcg(&g_inv[b], 1.0f / v);
            g_cnt[b] = 0;                                // reset for next replay
            unsigned int u = atom_add_acqrel(&g_final);  // release orders the stcg
            last_final = (u == (unsigned int)(B - 1));
        }
        last_final = __shfl_sync(0xffffffffu, last_final, 0);
        if (!last_final) return;
    }

    // ---- Global tail: one warp reduces 128 per-batch inverses ----
    {
        const float4* __restrict__ p = reinterpret_cast<const float4*>(g_inv);
        float4 v = __ldcg(p + lane);                     // 128 values
        float sv = (v.x + v.y) + (v.z + v.w);
        sv = warp_reduce(sv);
        if (lane == 0) {
            out[0] = sv * (1.0f / (float)B);
            g_final = 0;                                 // reset for next replay
        }
    }
}

extern "C" void kernel_launch(void* const* d_in, const int* in_sizes, int n_in,
                              void* d_out, int out_size) {
    const float* prob = (const float*)d_in[0];
    const float* H    = (const float*)d_in[1];
    if (in_sizes[0] != 2 * B * L) { prob = (const float*)d_in[1]; H = (const float*)d_in[0]; }

    fused_kernel<<<NBLK, 1024>>>(H, prob, (float*)d_out);
}

// round 8
// speedup vs baseline: 1.1828x; 1.1828x over previous
#include <cuda_runtime.h>
#include <math.h>

#define B 128
#define L 1024
#define NBLK (B * L / 8)      // 16384 blocks, 128 per batch
#define P_TX 10.0f
#define P_NOISE 6.2946e-14f

__device__ float g_bsum[NBLK];            // per-block partial sums of R
__device__ float g_inv[B];                // per-batch 1/sum
__device__ unsigned int g_cnt[B] = {};    // per-batch completion counters
__device__ unsigned int g_final = 0;      // final completion counter

__inline__ __device__ float warp_reduce(float v) {
    #pragma unroll
    for (int o = 16; o; o >>= 1) v += __shfl_down_sync(0xffffffffu, v, o);
    return v;
}

__device__ __forceinline__ unsigned int atom_add_acqrel(unsigned int* p) {
    unsigned int old;
    asm volatile("atom.add.acq_rel.gpu.u32 %0, [%1], 1;"
                 : "=r"(old) : "l"(p) : "memory");
    return old;
}

// Single fused kernel: warp-per-row mainloop + hierarchical fence-free finalize.
__global__ void __launch_bounds__(256) fused_kernel(const float* __restrict__ H,
                                                    const float* __restrict__ prob,
                                                    float* __restrict__ out) {
    const int row  = blockIdx.x * 8 + (threadIdx.x >> 5);   // global row in [0, B*L)
    const int lane = threadIdx.x & 31;
    const int b    = blockIdx.x >> 7;                        // 128 blocks per batch
    const int k    = row & (L - 1);

    __shared__ float sPy[L];            // P * y[b, :]  (4 KB)

    // Stage Py: 256 threads x 2 coalesced float4 loads (2 y-values per float4)
    {
        const float4* __restrict__ p4 =
            reinterpret_cast<const float4*>(prob + 2 * (size_t)b * L);
        #pragma unroll
        for (int i = 0; i < 2; i++) {
            int j = i * 256 + threadIdx.x;       // float4 index in [0, 512)
            float4 v = __ldg(p4 + j);
            sPy[2 * j]     = P_TX * v.y;
            sPy[2 * j + 1] = P_TX * v.w;
        }
    }
    __syncthreads();

    const float4* __restrict__ h4 = reinterpret_cast<const float4*>(H + (size_t)row * L);
    const float4* __restrict__ s4 = reinterpret_cast<const float4*>(sPy);

    float acc = 0.0f;
    #pragma unroll
    for (int i = 0; i < 8; i++) {
        const int t = i * 32 + lane;
        float4 h = __ldcs(h4 + t);      // evict-first: H is read exactly once
        float4 p = s4[t];               // conflict-free LDS.128
        acc = fmaf(h.x * h.x, p.x, acc);
        acc = fmaf(h.y * h.y, p.y, acc);
        acc = fmaf(h.z * h.z, p.z, acc);
        acc = fmaf(h.w * h.w, p.w, acc);
    }

    acc = warp_reduce(acc);

    __shared__ float sR[8];
    if (lane == 0) {
        float d      = __ldg(H + (size_t)row * L + k);   // diagonal (L2 hit)
        float signal = d * d * sPy[k];
        float interf = acc - signal;
        sR[threadIdx.x >> 5] =
            log1pf(signal / (interf + P_NOISE)) * 1.4426950408889634f;
    }
    __syncthreads();

    __shared__ bool sLastInBatch;
    if (threadIdx.x == 0) {
        float s = 0.0f;
        #pragma unroll
        for (int w = 0; w < 8; w++) s += sR[w];
        __stcg(&g_bsum[blockIdx.x], s);                  // L2 = coherence point
        unsigned int t = atom_add_acqrel(&g_cnt[b]);     // release orders the stcg
        sLastInBatch = (t == 127u);
    }
    __syncthreads();

    if (!sLastInBatch) return;

    // ---- Per-batch tail (warp 0 of this batch's last-done block) ----
    if (threadIdx.x >= 32) return;

    {
        const float4* __restrict__ p =
            reinterpret_cast<const float4*>(g_bsum + b * 128);
        float4 v = __ldcg(p + lane);                     // 32 lanes * 4 = 128 partials
        float s = (v.x + v.y) + (v.z + v.w);
        s = warp_reduce(s);

        bool last_final = false;
        if (lane == 0) {
            __stcg(&g_inv[b], 1.0f / s);
            g_cnt[b] = 0;                                // reset for next replay
            unsigned int u = atom_add_acqrel(&g_final);  // release orders the stcg
            last_final = (u == (unsigned int)(B - 1));
        }
        last_final = __shfl_sync(0xffffffffu, last_final, 0);
        if (!last_final) return;
    }

    // ---- Global tail: one warp reduces 128 per-batch inverses ----
    {
        const float4* __restrict__ p = reinterpret_cast<const float4*>(g_inv);
        float4 v = __ldcg(p + lane);                     // 128 values
        float s = (v.x + v.y) + (v.z + v.w);
        s = warp_reduce(s);
        if (lane == 0) {
            out[0] = s * (1.0f / (float)B);
            g_final = 0;                                 // reset for next replay
        }
    }
}

extern "C" void kernel_launch(void* const* d_in, const int* in_sizes, int n_in,
                              void* d_out, int out_size) {
    const float* prob = (const float*)d_in[0];
    const float* H    = (const float*)d_in[1];
    if (in_sizes[0] != 2 * B * L) { prob = (const float*)d_in[1]; H = (const float*)d_in[0]; }

    fused_kernel<<<NBLK, 256>>>(H, prob, (float*)d_out);
}

// round 9
// speedup vs baseline: 1.2155x; 1.0276x over previous
#include <cuda_runtime.h>
#include <math.h>

#define B 128
#define L 1024
#define CTAS 1024             // 8 CTAs per batch, 128 rows per CTA
#define GROUPS 16             // 16 groups x 8 rows = 128 rows per CTA
#define P_TX 10.0f
#define P_NOISE 6.2946e-14f

__device__ float g_bsum[CTAS];            // per-CTA partial sums of R
__device__ float g_inv[B];                // per-batch 1/sum
__device__ unsigned int g_cnt[B] = {};    // per-batch completion counters (to 8)
__device__ unsigned int g_final = 0;      // final completion counter (to 128)

__inline__ __device__ float warp_reduce(float v) {
    #pragma unroll
    for (int o = 16; o; o >>= 1) v += __shfl_down_sync(0xffffffffu, v, o);
    return v;
}

__device__ __forceinline__ unsigned int atom_add_acqrel(unsigned int* p) {
    unsigned int old;
    asm volatile("atom.add.acq_rel.gpu.u32 %0, [%1], 1;"
                 : "=r"(old) : "l"(p) : "memory");
    return old;
}

// Persistent-style: each CTA owns 128 consecutive rows of one batch.
// Stage Py once, then 16 row-groups (warp-per-row), then fence-free finalize.
__global__ void __launch_bounds__(256) fused_kernel(const float* __restrict__ H,
                                                    const float* __restrict__ prob,
                                                    float* __restrict__ out) {
    const int wid   = threadIdx.x >> 5;
    const int lane  = threadIdx.x & 31;
    const int b     = blockIdx.x >> 3;                  // 8 CTAs per batch
    const int rbase = blockIdx.x * 128;                 // first global row of this CTA

    __shared__ float sPy[L];            // P * y[b, :]  (4 KB), staged ONCE
    __shared__ float sR[8];

    {
        const float4* __restrict__ p4 =
            reinterpret_cast<const float4*>(prob + 2 * (size_t)b * L);
        #pragma unroll
        for (int i = 0; i < 2; i++) {
            int j = i * 256 + threadIdx.x;              // float4 index in [0, 512)
            float4 v = __ldg(p4 + j);
            sPy[2 * j]     = P_TX * v.y;
            sPy[2 * j + 1] = P_TX * v.w;
        }
    }
    __syncthreads();

    const float4* __restrict__ s4 = reinterpret_cast<const float4*>(sPy);

    float rsum = 0.0f;                  // lane 0 of each warp accumulates R over groups

    #pragma unroll 1
    for (int g = 0; g < GROUPS; g++) {
        const int row = rbase + g * 8 + wid;            // global row
        const int k   = row & (L - 1);
        const float4* __restrict__ h4 =
            reinterpret_cast<const float4*>(H + (size_t)row * L);

        float acc = 0.0f;
        #pragma unroll
        for (int i = 0; i < 8; i++) {
            const int t = i * 32 + lane;
            float4 h = __ldcs(h4 + t);  // evict-first: H read exactly once
            float4 p = s4[t];           // conflict-free LDS.128
            acc = fmaf(h.x * h.x, p.x, acc);
            acc = fmaf(h.y * h.y, p.y, acc);
            acc = fmaf(h.z * h.z, p.z, acc);
            acc = fmaf(h.w * h.w, p.w, acc);
        }
        acc = warp_reduce(acc);

        if (lane == 0) {
            float d      = __ldg(H + (size_t)row * L + k);   // diagonal (L2 hit)
            float signal = d * d * sPy[k];
            float interf = acc - signal;
            rsum += log1pf(signal / (interf + P_NOISE)) * 1.4426950408889634f;
        }
    }

    if (lane == 0) sR[wid] = rsum;
    __syncthreads();

    if (wid != 0) return;

    // Warp 0: combine 8 warp sums, publish partial, run completion protocol.
    float s = (lane < 8) ? sR[lane] : 0.0f;
    s = warp_reduce(s);

    bool last_in_batch = false;
    if (lane == 0) {
        __stcg(&g_bsum[blockIdx.x], s);                 // L2 = coherence point
        unsigned int t = atom_add_acqrel(&g_cnt[b]);    // release orders the stcg
        last_in_batch = (t == 7u);
    }
    last_in_batch = __shfl_sync(0xffffffffu, last_in_batch, 0);
    if (!last_in_batch) return;

    // ---- Per-batch tail: reduce this batch's 8 partials ----
    {
        float v = (lane < 8) ? __ldcg(g_bsum + b * 8 + lane) : 0.0f;
        v = warp_reduce(v);

        bool last_final = false;
        if (lane == 0) {
            __stcg(&g_inv[b], 1.0f / v);
            g_cnt[b] = 0;                               // reset for next replay
            unsigned int u = atom_add_acqrel(&g_final); // release orders the stcg
            last_final = (u == (unsigned int)(B - 1));
        }
        last_final = __shfl_sync(0xffffffffu, last_final, 0);
        if (!last_final) return;
    }

    // ---- Global tail: one warp reduces 128 per-batch inverses ----
    {
        const float4* __restrict__ p = reinterpret_cast<const float4*>(g_inv);
        float4 v = __ldcg(p + lane);                    // 128 values
        float sv = (v.x + v.y) + (v.z + v.w);
        sv = warp_reduce(sv);
        if (lane == 0) {
            out[0] = sv * (1.0f / (float)B);
            g_final = 0;                                // reset for next replay
        }
    }
}

extern "C" void kernel_launch(void* const* d_in, const int* in_sizes, int n_in,
                              void* d_out, int out_size) {
    const float* prob = (const float*)d_in[0];
    const float* H    = (const float*)d_in[1];
    if (in_sizes[0] != 2 * B * L) { prob = (const float*)d_in[1]; H = (const float*)d_in[0]; }

    fused_kernel<<<CTAS, 256>>>(H, prob, (float*)d_out);
}